// round 15
// baseline (speedup 1.0000x reference)
#include <cuda_runtime.h>
#include <cuda_fp16.h>
#include <math.h>
#include <stdint.h>

// ---------------------------------------------------------------------------
// XAIGuidedTransformerLayer on GB300 (sm_103a) — fp16 mma.sync GEMMs (fp32 acc).
// Round 15: BM128 x BN64 tiles (4 warps, 64x32 warp tile, ~130 regs) ->
// 3 CTAs/SM, 12 warps/SM. ncu showed tensor pipe starved at 8 warps/SM.
// B=8, S=2048, D=512.
// ---------------------------------------------------------------------------

#define BATCH 8
#define SEQ   2048
#define DIM   512
#define ROWS  (BATCH * SEQ)        // 16384
#define RMS_EPS 1.1920928955078125e-7f

// ---- scratch (device globals: allocation-free) ----
__device__ __half g_p16   [(size_t)BATCH * SEQ * SEQ];   // 67 MB fp16 exp(scores)
__device__ __half g_h16   [(size_t)ROWS * DIM];
__device__ __half g_g16   [(size_t)ROWS * DIM];
__device__ __half g_q16   [(size_t)ROWS * DIM];          // reused as s16
__device__ __half g_k16   [(size_t)ROWS * DIM];          // reused as ff16
__device__ __half g_xT16  [(size_t)ROWS * DIM];          // per-batch [D,S]
__device__ __half g_W1P   [(size_t)2 * DIM * DIM];       // [2D, D] col-interleaved
__device__ __half g_W2T   [(size_t)DIM * DIM];           // [D, D]

// ---------------------------------------------------------------------------
__device__ __forceinline__ uint32_t smem_u32(const void* p) {
    uint32_t a;
    asm("{ .reg .u64 t; cvta.to.shared.u64 t, %1; cvt.u32.u64 %0, t; }" : "=r"(a) : "l"(p));
    return a;
}

#define CP_ASYNC16(dst, src) \
    asm volatile("cp.async.cg.shared.global [%0], [%1], 16;" :: "r"(dst), "l"(src))
#define CP_COMMIT() asm volatile("cp.async.commit_group;")
#define CP_WAIT2()  asm volatile("cp.async.wait_group 2;")
#define CP_WAIT1()  asm volatile("cp.async.wait_group 1;")
#define CP_WAIT0()  asm volatile("cp.async.wait_group 0;")

#define LDSM4(r0, r1, r2, r3, addr) \
    asm volatile("ldmatrix.sync.aligned.m8n8.x4.shared.b16 {%0,%1,%2,%3}, [%4];" \
        : "=r"(r0), "=r"(r1), "=r"(r2), "=r"(r3) : "r"(addr))

#define MMA_F16(d, a0, a1, a2, a3, b0, b1) \
    asm volatile("mma.sync.aligned.m16n8k16.row.col.f32.f16.f16.f32 " \
        "{%0,%1,%2,%3}, {%4,%5,%6,%7}, {%8,%9}, {%0,%1,%2,%3};" \
        : "+f"((d)[0]), "+f"((d)[1]), "+f"((d)[2]), "+f"((d)[3]) \
        : "r"(a0), "r"(a1), "r"(a2), "r"(a3), "r"(b0), "r"(b1))

__device__ __forceinline__ float gelu_exact(float x) {
    return 0.5f * x * (1.0f + erff(x * 0.70710678118654752440f));
}

// ===========================================================================
// 128x64 tile GEMM (4 warps 2x2, warp tile 64x32), 4-stage single-barrier loop.
// MODE 1: fp16 out (alpha, optional fp32 bias).
// MODE 2: geglu out (W1 col-interleaved; output [M, N/2] fp16).
// MODE 3: fp16 out = exp(alpha * acc).
// MODE 4: rowsum(A) in mainloop; fp16 out = acc/rowsum + resid (x residual).
// ===========================================================================
#define BM 128
#define BN 64
#define BKK 32
#define AST 40                     // padded row stride in halves (80 B)
#define TILE_A (BM * 80)           // 10240 bytes
#define TILE_BB (BN * 80)          // 5120 bytes
#define STAGES 4
#define BS_BASE (STAGES * TILE_A)  // 40960
#define GEMM_SMEM   (STAGES * (TILE_A + TILE_BB))   // 61440 bytes
#define GEMM_SMEM_A (GEMM_SMEM + 512)               // + rowsum[128] floats

template<int MODE>
__global__ void __launch_bounds__(128, 3)
gemm_f16mma(const __half* __restrict__ A, const __half* __restrict__ B,
            const float* __restrict__ bias, void* __restrict__ Cv,
            int M, int N, int K,
            long long sA, long long sB, long long sC, float alpha,
            const float* __restrict__ resid)
{
    extern __shared__ char smem[];
    const uint32_t sm = smem_u32(smem);
    float* rowsum_sm = (float*)(smem + GEMM_SMEM);   // MODE 4 only (128 floats)

    const int tid  = threadIdx.x;
    const int wid  = tid >> 5;
    const int lane = tid & 31;
    const int wm   = wid & 1;      // row half
    const int wn   = wid >> 1;     // col half (0..1)

    A += (long long)blockIdx.z * sA;
    B += (long long)blockIdx.z * sB;
    const int row0 = blockIdx.y * BM;
    const int col0 = blockIdx.x * BN;

    // cp.async mapping: A 512 chunks (4/thread), B 256 chunks (2/thread)
    const int a_r0 = (tid + 0)   >> 2, a_c0 = ((tid + 0)   & 3);
    const int a_r1 = (tid + 128) >> 2, a_c1 = ((tid + 128) & 3);
    const int a_r2 = (tid + 256) >> 2, a_c2 = ((tid + 256) & 3);
    const int a_r3 = (tid + 384) >> 2, a_c3 = ((tid + 384) & 3);
    const int b_r0 = (tid + 0)   >> 2, b_c0 = ((tid + 0)   & 3);
    const int b_r1 = (tid + 128) >> 2, b_c1 = ((tid + 128) & 3);

    const int q  = lane >> 3, r8 = lane & 7;
    const int arow = (q & 1) * 8 + r8;
    const int acol16 = (q >> 1);
    const int brow = (q >> 1) * 8 + r8;
    const int bcol16 = (q & 1);

    const uint32_t a_base = sm + (wm * 64 + arow) * 80 + acol16 * 16;
    const uint32_t b_base = sm + BS_BASE + (wn * 32 + brow) * 80 + bcol16 * 16;

    float acc[4][4][4];
    #pragma unroll
    for (int i = 0; i < 4; i++)
        #pragma unroll
        for (int j = 0; j < 4; j++)
            #pragma unroll
            for (int v = 0; v < 4; v++) acc[i][j][v] = 0.0f;

    float rsum[4][2];
    if (MODE == 4) {
        #pragma unroll
        for (int i = 0; i < 4; i++) { rsum[i][0] = 0.0f; rsum[i][1] = 0.0f; }
    }

    const int KT = K / BKK;

    auto load_tile = [&](int kt, int buf) {
        const long long k0 = (long long)kt * BKK;
        uint32_t da = sm + buf * TILE_A;
        uint32_t db = sm + BS_BASE + buf * TILE_BB;
        CP_ASYNC16(da + a_r0 * 80 + a_c0 * 16, A + (long long)(row0 + a_r0) * K + k0 + a_c0 * 8);
        CP_ASYNC16(da + a_r1 * 80 + a_c1 * 16, A + (long long)(row0 + a_r1) * K + k0 + a_c1 * 8);
        CP_ASYNC16(da + a_r2 * 80 + a_c2 * 16, A + (long long)(row0 + a_r2) * K + k0 + a_c2 * 8);
        CP_ASYNC16(da + a_r3 * 80 + a_c3 * 16, A + (long long)(row0 + a_r3) * K + k0 + a_c3 * 8);
        CP_ASYNC16(db + b_r0 * 80 + b_c0 * 16, B + (long long)(col0 + b_r0) * K + k0 + b_c0 * 8);
        CP_ASYNC16(db + b_r1 * 80 + b_c1 * 16, B + (long long)(col0 + b_r1) * K + k0 + b_c1 * 8);
    };

    load_tile(0, 0); CP_COMMIT();
    load_tile(1, 1); CP_COMMIT();
    load_tile(2, 2); CP_COMMIT();

    for (int kt = 0; kt < KT; kt++) {
        const int rem = KT - 1 - kt;
        if (rem >= 2)      { CP_WAIT2(); }
        else if (rem == 1) { CP_WAIT1(); }
        else               { CP_WAIT0(); }
        __syncthreads();   // all warps done with buffer (kt+3)&3

        if (kt + 3 < KT) { load_tile(kt + 3, (kt + 3) & 3); CP_COMMIT(); }

        const uint32_t offA = (kt & 3) * TILE_A;
        const uint32_t offB = (kt & 3) * TILE_BB;

        #pragma unroll
        for (int s = 0; s < 2; s++) {
            uint32_t af[4][4];
            #pragma unroll
            for (int i = 0; i < 4; i++)
                LDSM4(af[i][0], af[i][1], af[i][2], af[i][3],
                      a_base + offA + i * (16 * 80) + s * 32);

            if (MODE == 4 && wn == 0) {
                // cheap rowsum on A frags (wid 0,1 cover all 128 rows)
                #pragma unroll
                for (int i = 0; i < 4; i++) {
                    __half2 s0 = __hadd2(*(const __half2*)&af[i][0],
                                         *(const __half2*)&af[i][2]);
                    __half2 s1 = __hadd2(*(const __half2*)&af[i][1],
                                         *(const __half2*)&af[i][3]);
                    float2 f0 = __half22float2(s0);
                    float2 f1 = __half22float2(s1);
                    rsum[i][0] += f0.x + f0.y;
                    rsum[i][1] += f1.x + f1.y;
                }
            }

            uint32_t bf[2][4];
            #pragma unroll
            for (int j = 0; j < 2; j++)
                LDSM4(bf[j][0], bf[j][1], bf[j][2], bf[j][3],
                      b_base + offB + j * (16 * 80) + s * 32);
            #pragma unroll
            for (int i = 0; i < 4; i++)
                #pragma unroll
                for (int jj = 0; jj < 4; jj++)
                    MMA_F16(acc[i][jj],
                            af[i][0], af[i][1], af[i][2], af[i][3],
                            bf[jj >> 1][(jj & 1) * 2], bf[jj >> 1][(jj & 1) * 2 + 1]);
        }
    }

    const int er = lane >> 2;
    const int ec = (lane & 3) * 2;

    if (MODE == 4) {
        if (wn == 0) {
            #pragma unroll
            for (int i = 0; i < 4; i++) {
                #pragma unroll
                for (int hh = 0; hh < 2; hh++) {
                    float v = rsum[i][hh];
                    v += __shfl_xor_sync(0xffffffff, v, 1);
                    v += __shfl_xor_sync(0xffffffff, v, 2);
                    if ((lane & 3) == 0)
                        rowsum_sm[wm * 64 + i * 16 + er + hh * 8] = v;
                }
            }
        }
        __syncthreads();
    }

    if (MODE == 1 || MODE == 3) {
        __half* C = (__half*)Cv + (long long)blockIdx.z * sC;
        #pragma unroll
        for (int i = 0; i < 4; i++) {
            const long long r0g = row0 + wm * 64 + i * 16 + er;
            #pragma unroll
            for (int jj = 0; jj < 4; jj++) {
                const int cg = col0 + wn * 32 + jj * 8 + ec;
                float v0, v1, v2, v3;
                if (MODE == 3) {
                    v0 = __expf(alpha * acc[i][jj][0]);
                    v1 = __expf(alpha * acc[i][jj][1]);
                    v2 = __expf(alpha * acc[i][jj][2]);
                    v3 = __expf(alpha * acc[i][jj][3]);
                } else {
                    float bx = 0.0f, by = 0.0f;
                    if (bias) { bx = bias[cg]; by = bias[cg + 1]; }
                    v0 = fmaf(alpha, acc[i][jj][0], bx);
                    v1 = fmaf(alpha, acc[i][jj][1], by);
                    v2 = fmaf(alpha, acc[i][jj][2], bx);
                    v3 = fmaf(alpha, acc[i][jj][3], by);
                }
                *(__half2*)(C + r0g * N + cg)       = __floats2half2_rn(v0, v1);
                *(__half2*)(C + (r0g + 8) * N + cg) = __floats2half2_rn(v2, v3);
            }
        }
    } else if (MODE == 4) {
        __half* C = (__half*)Cv + (long long)blockIdx.z * sC;
        const float* resb = resid + (long long)blockIdx.z * sC;
        #pragma unroll
        for (int i = 0; i < 4; i++) {
            const int rl = wm * 64 + i * 16 + er;
            const long long r0g = row0 + rl;
            const float inv0 = 1.0f / rowsum_sm[rl];
            const float inv1 = 1.0f / rowsum_sm[rl + 8];
            #pragma unroll
            for (int jj = 0; jj < 4; jj++) {
                const int cg = col0 + wn * 32 + jj * 8 + ec;
                float2 xv0 = *(const float2*)(resb + r0g * N + cg);
                float2 xv1 = *(const float2*)(resb + (r0g + 8) * N + cg);
                *(__half2*)(C + r0g * N + cg) =
                    __floats2half2_rn(fmaf(acc[i][jj][0], inv0, xv0.x),
                                      fmaf(acc[i][jj][1], inv0, xv0.y));
                *(__half2*)(C + (r0g + 8) * N + cg) =
                    __floats2half2_rn(fmaf(acc[i][jj][2], inv1, xv1.x),
                                      fmaf(acc[i][jj][3], inv1, xv1.y));
            }
        }
    } else {                  // MODE 2: geglu (pairs of n8 blocks: jj 0/1, 2/3)
        __half* C = (__half*)Cv;    // [M, N/2]
        const int NO = N >> 1;
        #pragma unroll
        for (int i = 0; i < 4; i++) {
            const long long r0g = row0 + wm * 64 + i * 16 + er;
            #pragma unroll
            for (int jj = 0; jj < 4; jj += 2) {
                const int oc = ((col0 + wn * 32 + jj * 8) >> 1) + ec;
                const float b1x = bias[oc];
                const float b1y = bias[oc + 1];
                const float b2x = bias[512 + oc];
                const float b2y = bias[512 + oc + 1];
                float g0 = gelu_exact(acc[i][jj][0] + b1x) * (acc[i][jj + 1][0] + b2x);
                float g1 = gelu_exact(acc[i][jj][1] + b1y) * (acc[i][jj + 1][1] + b2y);
                float g2 = gelu_exact(acc[i][jj][2] + b1x) * (acc[i][jj + 1][2] + b2x);
                float g3 = gelu_exact(acc[i][jj][3] + b1y) * (acc[i][jj + 1][3] + b2y);
                *(__half2*)(C + r0g * NO + oc)       = __floats2half2_rn(g0, g1);
                *(__half2*)(C + (r0g + 8) * NO + oc) = __floats2half2_rn(g2, g3);
            }
        }
    }
}

// ---------------------------------------------------------------------------
// fp32 -> fp16 convert for q and k in one launch (grid.y selects tensor)
// ---------------------------------------------------------------------------
__global__ void __launch_bounds__(256)
cvt2_f16_kernel(const float4* __restrict__ q, const float4* __restrict__ k,
                __half2* __restrict__ q16, __half2* __restrict__ k16, int n4)
{
    int i = blockIdx.x * 256 + threadIdx.x;
    if (i >= n4) return;
    const float4* in = blockIdx.y ? k : q;
    __half2* out = blockIdx.y ? k16 : q16;
    float4 v = in[i];
    out[i * 2 + 0] = __floats2half2_rn(v.x, v.y);
    out[i * 2 + 1] = __floats2half2_rn(v.z, v.w);
}

// ---------------------------------------------------------------------------
// Merged transpose prep (z selects tensor): z<8: x batch z; z=8: W1(PERM); z=9: W2.
// ---------------------------------------------------------------------------
__global__ void __launch_bounds__(256)
prep_transpose_kernel(const float* __restrict__ x,   __half* __restrict__ xT,
                      const float* __restrict__ W1,  __half* __restrict__ W1P,
                      const float* __restrict__ W2,  __half* __restrict__ W2T)
{
    __shared__ float t[32][33];
    const float* in; __half* out;
    int R, C; long long zoff = 0; int perm = 0;
    const int z = blockIdx.z;
    const int bx = blockIdx.x, by = blockIdx.y;
    if (z < 8) {
        in = x; out = xT; R = SEQ; C = DIM; zoff = (long long)z * R * C; perm = 0;
        if (bx >= C / 32 || by >= R / 32) return;
    } else if (z == 8) {
        in = W1; out = W1P; R = DIM; C = 2 * DIM; zoff = 0; perm = 1;
        if (bx >= C / 32 || by >= R / 32) return;
    } else {
        in = W2; out = W2T; R = DIM; C = DIM; zoff = 0; perm = 0;
        if (bx >= C / 32 || by >= R / 32) return;
    }

    const int c0 = bx * 32, r0 = by * 32;
    const int tx = threadIdx.x & 31, ty = threadIdx.x >> 5;
    #pragma unroll
    for (int i = 0; i < 4; i++) {
        int rr = r0 + ty + i * 8;
        t[ty + i * 8][tx] = in[zoff + (long long)rr * C + c0 + tx];
    }
    __syncthreads();
    #pragma unroll
    for (int i = 0; i < 4; i++) {
        int cc = c0 + ty + i * 8;
        int dr = cc;
        if (perm) {
            dr = (cc < 512) ? ((cc >> 3) << 4) + (cc & 7)
                            : (((cc - 512) >> 3) << 4) + 8 + ((cc - 512) & 7);
        }
        out[zoff + (long long)dr * R + r0 + tx] = __float2half_rn(t[tx][ty + i * 8]);
    }
}

// ---------------------------------------------------------------------------
// rmsnorm(s) * w.  s: fp16 (already includes residual). Writes fp16 h16.
// ---------------------------------------------------------------------------
__global__ void __launch_bounds__(128)
rmsnorm16_kernel(const __half* __restrict__ s16, const float* __restrict__ w,
                 __half* __restrict__ out16)
{
    const long long row = blockIdx.x;
    const int tid = threadIdx.x;
    const long long base = row * (long long)DIM + tid * 4;

    const __half2* sh = (const __half2*)(s16 + base);
    float2 a0 = __half22float2(sh[0]);
    float2 a1 = __half22float2(sh[1]);

    float ss = a0.x * a0.x + a0.y * a0.y + a1.x * a1.x + a1.y * a1.y;
    #pragma unroll
    for (int off = 16; off > 0; off >>= 1)
        ss += __shfl_xor_sync(0xffffffff, ss, off);

    __shared__ float red[4];
    const int wd = tid >> 5, lane = tid & 31;
    if (lane == 0) red[wd] = ss;
    __syncthreads();
    const float tot = red[0] + red[1] + red[2] + red[3];
    const float scale = rsqrtf(tot * (1.0f / (float)DIM) + RMS_EPS);

    float4 vw = *(const float4*)(w + tid * 4);
    __half2* t = (__half2*)(out16 + base);
    t[0] = __floats2half2_rn(a0.x * scale * vw.x, a0.y * scale * vw.y);
    t[1] = __floats2half2_rn(a1.x * scale * vw.z, a1.y * scale * vw.w);
}

// ---------------------------------------------------------------------------
// out = rmsnorm(a16 + b16) * w (fp32 out)
// ---------------------------------------------------------------------------
__global__ void __launch_bounds__(128)
add_rmsnorm16_kernel(const __half* __restrict__ a, const __half* __restrict__ b,
                     const float* __restrict__ w, float* __restrict__ out32)
{
    const long long row = blockIdx.x;
    const int tid = threadIdx.x;
    const long long base = row * (long long)DIM + tid * 4;

    const __half2* ah = (const __half2*)(a + base);
    const __half2* bh = (const __half2*)(b + base);
    float2 a0 = __half22float2(ah[0]);
    float2 a1 = __half22float2(ah[1]);
    float2 b0 = __half22float2(bh[0]);
    float2 b1 = __half22float2(bh[1]);

    float4 s;
    s.x = a0.x + b0.x; s.y = a0.y + b0.y; s.z = a1.x + b1.x; s.w = a1.y + b1.y;

    float ss = s.x * s.x + s.y * s.y + s.z * s.z + s.w * s.w;
    #pragma unroll
    for (int off = 16; off > 0; off >>= 1)
        ss += __shfl_xor_sync(0xffffffff, ss, off);

    __shared__ float red[4];
    const int wd = tid >> 5, lane = tid & 31;
    if (lane == 0) red[wd] = ss;
    __syncthreads();
    const float tot = red[0] + red[1] + red[2] + red[3];
    const float scale = rsqrtf(tot * (1.0f / (float)DIM) + RMS_EPS);

    float4 vw = *(const float4*)(w + tid * 4);
    float4 o;
    o.x = s.x * scale * vw.x;
    o.y = s.y * scale * vw.y;
    o.z = s.z * scale * vw.z;
    o.w = s.w * scale * vw.w;
    *(float4*)(out32 + base) = o;
}

// ---------------------------------------------------------------------------
extern "C" void kernel_launch(void* const* d_in, const int* in_sizes, int n_in,
                              void* d_out, int out_size)
{
    const float* x   = (const float*)d_in[0];
    const float* q   = (const float*)d_in[1];
    const float* k   = (const float*)d_in[2];
    const float* W1  = (const float*)d_in[3];
    const float* b1  = (const float*)d_in[4];
    const float* W2  = (const float*)d_in[5];
    const float* b2  = (const float*)d_in[6];
    const float* n1w = (const float*)d_in[7];
    const float* n2w = (const float*)d_in[8];
    float* out = (float*)d_out;

    __half *p16, *h16, *g16, *q16, *k16, *xT, *W1P, *W2T;
    cudaGetSymbolAddress((void**)&p16,    g_p16);
    cudaGetSymbolAddress((void**)&h16,    g_h16);
    cudaGetSymbolAddress((void**)&g16,    g_g16);
    cudaGetSymbolAddress((void**)&q16,    g_q16);
    cudaGetSymbolAddress((void**)&k16,    g_k16);
    cudaGetSymbolAddress((void**)&xT,     g_xT16);
    cudaGetSymbolAddress((void**)&W1P,    g_W1P);
    cudaGetSymbolAddress((void**)&W2T,    g_W2T);

    __half* s16  = q16;   // q16 dead after GEMM1
    __half* ff16 = k16;   // k16 dead after GEMM1

    static int s_attr_set = 0;
    if (!s_attr_set) {
        cudaFuncSetAttribute(gemm_f16mma<1>,
                             cudaFuncAttributeMaxDynamicSharedMemorySize, GEMM_SMEM);
        cudaFuncSetAttribute(gemm_f16mma<2>,
                             cudaFuncAttributeMaxDynamicSharedMemorySize, GEMM_SMEM);
        cudaFuncSetAttribute(gemm_f16mma<3>,
                             cudaFuncAttributeMaxDynamicSharedMemorySize, GEMM_SMEM);
        cudaFuncSetAttribute(gemm_f16mma<4>,
                             cudaFuncAttributeMaxDynamicSharedMemorySize, GEMM_SMEM_A);
        s_attr_set = 1;
    }

    const float inv_sqrt_d = 0.044194173824159216f;  // 1/sqrt(512)

    // prep: q,k -> fp16; x/W1/W2 transposes (merged)
    const int n4 = ROWS * DIM / 4;
    {
        dim3 g(n4 / 256, 2, 1);
        cvt2_f16_kernel<<<g, 256>>>((const float4*)q, (const float4*)k,
                                    (__half2*)q16, (__half2*)k16, n4);
    }
    {
        dim3 g(32, 64, 10);
        prep_transpose_kernel<<<g, 256>>>(x, xT, W1, W1P, W2, W2T);
    }

    // 1) p16 = exp(q @ k^T / sqrt(D))
    {
        dim3 grid(SEQ / BN, SEQ / BM, BATCH);
        gemm_f16mma<3><<<grid, 128, GEMM_SMEM>>>(
            q16, k16, nullptr, p16, SEQ, SEQ, DIM,
            (long long)SEQ * DIM, (long long)SEQ * DIM, (long long)SEQ * SEQ,
            inv_sqrt_d, nullptr);
    }

    // 2) s16 = x + (p16 @ xT^T) / rowsum(p16)
    {
        dim3 grid(DIM / BN, SEQ / BM, BATCH);
        gemm_f16mma<4><<<grid, 128, GEMM_SMEM_A>>>(
            p16, xT, nullptr, s16, SEQ, DIM, SEQ,
            (long long)SEQ * SEQ, (long long)SEQ * DIM, (long long)SEQ * DIM,
            1.0f, x);
    }

    // 3) h16 = rmsnorm(s16) * n1w
    rmsnorm16_kernel<<<ROWS, 128>>>(s16, n1w, h16);

    // 4+5) g16 = geglu(h16 @ W1P^T + b1)
    {
        dim3 grid((2 * DIM) / BN, ROWS / BM, 1);
        gemm_f16mma<2><<<grid, 128, GEMM_SMEM>>>(
            h16, W1P, b1, g16, ROWS, 2 * DIM, DIM, 0, 0, 0, 1.0f, nullptr);
    }

    // 6) ff16 = g16 @ W2T^T + b2
    {
        dim3 grid(DIM / BN, ROWS / BM, 1);
        gemm_f16mma<1><<<grid, 128, GEMM_SMEM>>>(
            g16, W2T, b2, ff16, ROWS, DIM, DIM, 0, 0, 0, 1.0f, nullptr);
    }

    // 7) out = rmsnorm(h16 + ff16, n2w) -> fp32 d_out
    add_rmsnorm16_kernel<<<ROWS, 128>>>(h16, ff16, n2w, out);
}

// round 16
// speedup vs baseline: 1.0538x; 1.0538x over previous
#include <cuda_runtime.h>
#include <cuda_fp16.h>
#include <math.h>
#include <stdint.h>

// ---------------------------------------------------------------------------
// XAIGuidedTransformerLayer on GB300 (sm_103a) — fp16 mma.sync GEMMs (fp32 acc).
// Round 16: R11 (best) + merged prep transpose + prep overlapped with GEMM1
// on a forked side stream (graph-capturable fork/join).
// B=8, S=2048, D=512.
// ---------------------------------------------------------------------------

#define BATCH 8
#define SEQ   2048
#define DIM   512
#define ROWS  (BATCH * SEQ)        // 16384
#define RMS_EPS 1.1920928955078125e-7f

// ---- scratch (device globals: allocation-free) ----
__device__ __half g_p16   [(size_t)BATCH * SEQ * SEQ];   // 67 MB fp16 exp(scores)
__device__ __half g_h16   [(size_t)ROWS * DIM];
__device__ __half g_g16   [(size_t)ROWS * DIM];
__device__ __half g_q16   [(size_t)ROWS * DIM];          // reused as attn16
__device__ __half g_k16   [(size_t)ROWS * DIM];          // reused as ff16
__device__ __half g_xT16  [(size_t)ROWS * DIM];          // per-batch [D,S]
__device__ __half g_W1P   [(size_t)2 * DIM * DIM];       // [2D, D] col-interleaved
__device__ __half g_W2T   [(size_t)DIM * DIM];           // [D, D]

// ---------------------------------------------------------------------------
__device__ __forceinline__ uint32_t smem_u32(const void* p) {
    uint32_t a;
    asm("{ .reg .u64 t; cvta.to.shared.u64 t, %1; cvt.u32.u64 %0, t; }" : "=r"(a) : "l"(p));
    return a;
}

#define CP_ASYNC16(dst, src) \
    asm volatile("cp.async.cg.shared.global [%0], [%1], 16;" :: "r"(dst), "l"(src))
#define CP_COMMIT() asm volatile("cp.async.commit_group;")
#define CP_WAIT2()  asm volatile("cp.async.wait_group 2;")
#define CP_WAIT1()  asm volatile("cp.async.wait_group 1;")
#define CP_WAIT0()  asm volatile("cp.async.wait_group 0;")

#define LDSM4(r0, r1, r2, r3, addr) \
    asm volatile("ldmatrix.sync.aligned.m8n8.x4.shared.b16 {%0,%1,%2,%3}, [%4];" \
        : "=r"(r0), "=r"(r1), "=r"(r2), "=r"(r3) : "r"(addr))

#define MMA_F16(d, a0, a1, a2, a3, b0, b1) \
    asm volatile("mma.sync.aligned.m16n8k16.row.col.f32.f16.f16.f32 " \
        "{%0,%1,%2,%3}, {%4,%5,%6,%7}, {%8,%9}, {%0,%1,%2,%3};" \
        : "+f"((d)[0]), "+f"((d)[1]), "+f"((d)[2]), "+f"((d)[3]) \
        : "r"(a0), "r"(a1), "r"(a2), "r"(a3), "r"(b0), "r"(b1))

__device__ __forceinline__ float gelu_exact(float x) {
    return 0.5f * x * (1.0f + erff(x * 0.70710678118654752440f));
}

// ===========================================================================
// 128x128 tile GEMM (4 warps, warp tile 64x64), 4-stage single-barrier loop.
// MODE 1: fp16 out (alpha, optional fp32 bias).
// MODE 2: geglu out (W1 col-interleaved; output [M, N/2] fp16).
// MODE 3: fp16 out = exp(alpha * acc)    (attention scores -> e-values)
// MODE 4: rowsum(A) in mainloop; fp16 out = acc / rowsum   (attention PV)
// ===========================================================================
#define BM 128
#define BN 128
#define BKK 32
#define AST 40                     // padded row stride in halves (80 B)
#define TILE_B (BM * AST * 2)      // 10240 bytes per operand buffer
#define STAGES 4
#define BS_BASE (STAGES * TILE_B)
#define GEMM_SMEM   (2 * STAGES * TILE_B)        // 81920 bytes
#define GEMM_SMEM_A (GEMM_SMEM + 512)            // + rowsum[128] floats

template<int MODE>
__global__ void __launch_bounds__(128, 2)
gemm_f16mma(const __half* __restrict__ A, const __half* __restrict__ B,
            const float* __restrict__ bias, void* __restrict__ Cv,
            int M, int N, int K,
            long long sA, long long sB, long long sC, float alpha)
{
    extern __shared__ char smem[];
    const uint32_t sm = smem_u32(smem);
    float* rowsum_sm = (float*)(smem + GEMM_SMEM);   // MODE 4 only (128 floats)

    const int tid  = threadIdx.x;
    const int wid  = tid >> 5;
    const int lane = tid & 31;
    const int wm   = wid & 1;
    const int wn   = wid >> 1;

    A += (long long)blockIdx.z * sA;
    B += (long long)blockIdx.z * sB;
    const int row0 = blockIdx.y * BM;
    const int col0 = blockIdx.x * BN;

    const int c_r0 = (tid + 0)   >> 2, c_c0 = ((tid + 0)   & 3);
    const int c_r1 = (tid + 128) >> 2, c_c1 = ((tid + 128) & 3);
    const int c_r2 = (tid + 256) >> 2, c_c2 = ((tid + 256) & 3);
    const int c_r3 = (tid + 384) >> 2, c_c3 = ((tid + 384) & 3);

    const int q  = lane >> 3, r8 = lane & 7;
    const int arow = (q & 1) * 8 + r8;
    const int acol16 = (q >> 1);
    const int brow = (q >> 1) * 8 + r8;
    const int bcol16 = (q & 1);

    const uint32_t a_base = sm + (wm * 64 + arow) * (AST * 2) + acol16 * 16;
    const uint32_t b_base = sm + BS_BASE + (wn * 64 + brow) * (AST * 2) + bcol16 * 16;

    float acc[4][8][4];
    #pragma unroll
    for (int i = 0; i < 4; i++)
        #pragma unroll
        for (int j = 0; j < 8; j++)
            #pragma unroll
            for (int v = 0; v < 4; v++) acc[i][j][v] = 0.0f;

    float rsum[4][2];
    if (MODE == 4) {
        #pragma unroll
        for (int i = 0; i < 4; i++) { rsum[i][0] = 0.0f; rsum[i][1] = 0.0f; }
    }

    const int KT = K / BKK;

    auto load_tile = [&](int kt, int buf) {
        const long long k0 = (long long)kt * BKK;
        uint32_t da = sm + buf * TILE_B;
        uint32_t db = sm + BS_BASE + buf * TILE_B;
        CP_ASYNC16(da + c_r0 * 80 + c_c0 * 16, A + (long long)(row0 + c_r0) * K + k0 + c_c0 * 8);
        CP_ASYNC16(da + c_r1 * 80 + c_c1 * 16, A + (long long)(row0 + c_r1) * K + k0 + c_c1 * 8);
        CP_ASYNC16(da + c_r2 * 80 + c_c2 * 16, A + (long long)(row0 + c_r2) * K + k0 + c_c2 * 8);
        CP_ASYNC16(da + c_r3 * 80 + c_c3 * 16, A + (long long)(row0 + c_r3) * K + k0 + c_c3 * 8);
        CP_ASYNC16(db + c_r0 * 80 + c_c0 * 16, B + (long long)(col0 + c_r0) * K + k0 + c_c0 * 8);
        CP_ASYNC16(db + c_r1 * 80 + c_c1 * 16, B + (long long)(col0 + c_r1) * K + k0 + c_c1 * 8);
        CP_ASYNC16(db + c_r2 * 80 + c_c2 * 16, B + (long long)(col0 + c_r2) * K + k0 + c_c2 * 8);
        CP_ASYNC16(db + c_r3 * 80 + c_c3 * 16, B + (long long)(col0 + c_r3) * K + k0 + c_c3 * 8);
    };

    load_tile(0, 0); CP_COMMIT();
    load_tile(1, 1); CP_COMMIT();
    load_tile(2, 2); CP_COMMIT();

    for (int kt = 0; kt < KT; kt++) {
        const int rem = KT - 1 - kt;
        if (rem >= 2)      { CP_WAIT2(); }
        else if (rem == 1) { CP_WAIT1(); }
        else               { CP_WAIT0(); }
        __syncthreads();

        if (kt + 3 < KT) { load_tile(kt + 3, (kt + 3) & 3); CP_COMMIT(); }

        const uint32_t off = (kt & 3) * TILE_B;

        #pragma unroll
        for (int s = 0; s < 2; s++) {
            uint32_t af[4][4];
            #pragma unroll
            for (int i = 0; i < 4; i++)
                LDSM4(af[i][0], af[i][1], af[i][2], af[i][3],
                      a_base + off + i * (16 * AST * 2) + s * 32);

            if (MODE == 4) {
                if (wn == 0) {
                    #pragma unroll
                    for (int i = 0; i < 4; i++) {
                        __half2 s0 = __hadd2(*(const __half2*)&af[i][0],
                                             *(const __half2*)&af[i][2]);
                        __half2 s1 = __hadd2(*(const __half2*)&af[i][1],
                                             *(const __half2*)&af[i][3]);
                        float2 f0 = __half22float2(s0);
                        float2 f1 = __half22float2(s1);
                        rsum[i][0] += f0.x + f0.y;
                        rsum[i][1] += f1.x + f1.y;
                    }
                }
            }

            uint32_t bf[4][4];
            #pragma unroll
            for (int j = 0; j < 4; j++)
                LDSM4(bf[j][0], bf[j][1], bf[j][2], bf[j][3],
                      b_base + off + j * (16 * AST * 2) + s * 32);
            #pragma unroll
            for (int i = 0; i < 4; i++)
                #pragma unroll
                for (int jj = 0; jj < 8; jj++)
                    MMA_F16(acc[i][jj],
                            af[i][0], af[i][1], af[i][2], af[i][3],
                            bf[jj >> 1][(jj & 1) * 2], bf[jj >> 1][(jj & 1) * 2 + 1]);
        }
    }

    const int er = lane >> 2;
    const int ec = (lane & 3) * 2;

    if (MODE == 4) {
        if (wn == 0) {
            #pragma unroll
            for (int i = 0; i < 4; i++) {
                #pragma unroll
                for (int hh = 0; hh < 2; hh++) {
                    float v = rsum[i][hh];
                    v += __shfl_xor_sync(0xffffffff, v, 1);
                    v += __shfl_xor_sync(0xffffffff, v, 2);
                    if ((lane & 3) == 0)
                        rowsum_sm[wm * 64 + i * 16 + er + hh * 8] = v;
                }
            }
        }
        __syncthreads();
    }

    if (MODE == 1 || MODE == 3) {
        __half* C = (__half*)Cv + (long long)blockIdx.z * sC;
        #pragma unroll
        for (int i = 0; i < 4; i++) {
            const long long r0g = row0 + wm * 64 + i * 16 + er;
            #pragma unroll
            for (int jj = 0; jj < 8; jj++) {
                const int cg = col0 + wn * 64 + jj * 8 + ec;
                float v0, v1, v2, v3;
                if (MODE == 3) {
                    v0 = __expf(alpha * acc[i][jj][0]);
                    v1 = __expf(alpha * acc[i][jj][1]);
                    v2 = __expf(alpha * acc[i][jj][2]);
                    v3 = __expf(alpha * acc[i][jj][3]);
                } else {
                    float bx = 0.0f, by = 0.0f;
                    if (bias) { bx = bias[cg]; by = bias[cg + 1]; }
                    v0 = fmaf(alpha, acc[i][jj][0], bx);
                    v1 = fmaf(alpha, acc[i][jj][1], by);
                    v2 = fmaf(alpha, acc[i][jj][2], bx);
                    v3 = fmaf(alpha, acc[i][jj][3], by);
                }
                *(__half2*)(C + r0g * N + cg)       = __floats2half2_rn(v0, v1);
                *(__half2*)(C + (r0g + 8) * N + cg) = __floats2half2_rn(v2, v3);
            }
        }
    } else if (MODE == 4) {
        __half* C = (__half*)Cv + (long long)blockIdx.z * sC;
        #pragma unroll
        for (int i = 0; i < 4; i++) {
            const int rl = wm * 64 + i * 16 + er;
            const long long r0g = row0 + rl;
            const float inv0 = 1.0f / rowsum_sm[rl];
            const float inv1 = 1.0f / rowsum_sm[rl + 8];
            #pragma unroll
            for (int jj = 0; jj < 8; jj++) {
                const int cg = col0 + wn * 64 + jj * 8 + ec;
                *(__half2*)(C + r0g * N + cg) =
                    __floats2half2_rn(acc[i][jj][0] * inv0, acc[i][jj][1] * inv0);
                *(__half2*)(C + (r0g + 8) * N + cg) =
                    __floats2half2_rn(acc[i][jj][2] * inv1, acc[i][jj][3] * inv1);
            }
        }
    } else {                  // MODE 2: geglu epilogue
        __half* C = (__half*)Cv;    // [M, N/2]
        const int NO = N >> 1;
        #pragma unroll
        for (int i = 0; i < 4; i++) {
            const long long r0g = row0 + wm * 64 + i * 16 + er;
            #pragma unroll
            for (int jj = 0; jj < 8; jj += 2) {
                const int oc = ((col0 + wn * 64 + jj * 8) >> 1) + ec;
                const float b1x = bias[oc];
                const float b1y = bias[oc + 1];
                const float b2x = bias[512 + oc];
                const float b2y = bias[512 + oc + 1];
                float g0 = gelu_exact(acc[i][jj][0] + b1x) * (acc[i][jj + 1][0] + b2x);
                float g1 = gelu_exact(acc[i][jj][1] + b1y) * (acc[i][jj + 1][1] + b2y);
                float g2 = gelu_exact(acc[i][jj][2] + b1x) * (acc[i][jj + 1][2] + b2x);
                float g3 = gelu_exact(acc[i][jj][3] + b1y) * (acc[i][jj + 1][3] + b2y);
                *(__half2*)(C + r0g * NO + oc)       = __floats2half2_rn(g0, g1);
                *(__half2*)(C + (r0g + 8) * NO + oc) = __floats2half2_rn(g2, g3);
            }
        }
    }
}

// ---------------------------------------------------------------------------
// fp32 -> fp16 convert for q and k in one launch (grid.y selects tensor)
// ---------------------------------------------------------------------------
__global__ void __launch_bounds__(256)
cvt2_f16_kernel(const float4* __restrict__ q, const float4* __restrict__ k,
                __half2* __restrict__ q16, __half2* __restrict__ k16, int n4)
{
    int i = blockIdx.x * 256 + threadIdx.x;
    if (i >= n4) return;
    const float4* in = blockIdx.y ? k : q;
    __half2* out = blockIdx.y ? k16 : q16;
    float4 v = in[i];
    out[i * 2 + 0] = __floats2half2_rn(v.x, v.y);
    out[i * 2 + 1] = __floats2half2_rn(v.z, v.w);
}

// ---------------------------------------------------------------------------
// Merged transpose prep (z selects tensor): z<8: x batch z; z=8: W1(PERM); z=9: W2.
// ---------------------------------------------------------------------------
__global__ void __launch_bounds__(256)
prep_transpose_kernel(const float* __restrict__ x,   __half* __restrict__ xT,
                      const float* __restrict__ W1,  __half* __restrict__ W1P,
                      const float* __restrict__ W2,  __half* __restrict__ W2T)
{
    __shared__ float t[32][33];
    const float* in; __half* out;
    int R, C; long long zoff = 0; int perm = 0;
    const int z = blockIdx.z;
    const int bx = blockIdx.x, by = blockIdx.y;
    if (z < 8) {
        in = x; out = xT; R = SEQ; C = DIM; zoff = (long long)z * R * C; perm = 0;
        if (bx >= C / 32 || by >= R / 32) return;
    } else if (z == 8) {
        in = W1; out = W1P; R = DIM; C = 2 * DIM; zoff = 0; perm = 1;
        if (bx >= C / 32 || by >= R / 32) return;
    } else {
        in = W2; out = W2T; R = DIM; C = DIM; zoff = 0; perm = 0;
        if (bx >= C / 32 || by >= R / 32) return;
    }

    const int c0 = bx * 32, r0 = by * 32;
    const int tx = threadIdx.x & 31, ty = threadIdx.x >> 5;
    #pragma unroll
    for (int i = 0; i < 4; i++) {
        int rr = r0 + ty + i * 8;
        t[ty + i * 8][tx] = in[zoff + (long long)rr * C + c0 + tx];
    }
    __syncthreads();
    #pragma unroll
    for (int i = 0; i < 4; i++) {
        int cc = c0 + ty + i * 8;
        int dr = cc;
        if (perm) {
            dr = (cc < 512) ? ((cc >> 3) << 4) + (cc & 7)
                            : (((cc - 512) >> 3) << 4) + 8 + ((cc - 512) & 7);
        }
        out[zoff + (long long)dr * R + r0 + tx] = __float2half_rn(t[tx][ty + i * 8]);
    }
}

// ---------------------------------------------------------------------------
// rmsnorm(a + b) * w.  a: fp32 (A16=0) or fp16 (A16=1); b: fp16.
// ---------------------------------------------------------------------------
template<int A16>
__global__ void __launch_bounds__(128)
add_rmsnorm_kernel(const void* __restrict__ av, const __half* __restrict__ b,
                   const float* __restrict__ w, float* __restrict__ out32,
                   __half* __restrict__ out16)
{
    const long long row = blockIdx.x;
    const int tid = threadIdx.x;
    const long long base = row * (long long)DIM + tid * 4;

    float4 va;
    if (A16) {
        const __half2* ah = (const __half2*)((const __half*)av + base);
        float2 a0 = __half22float2(ah[0]);
        float2 a1 = __half22float2(ah[1]);
        va = make_float4(a0.x, a0.y, a1.x, a1.y);
    } else {
        va = *(const float4*)((const float*)av + base);
    }
    const __half2* bh = (const __half2*)(b + base);
    float2 b0 = __half22float2(bh[0]);
    float2 b1 = __half22float2(bh[1]);

    float4 s;
    s.x = va.x + b0.x; s.y = va.y + b0.y; s.z = va.z + b1.x; s.w = va.w + b1.y;

    float ss = s.x * s.x + s.y * s.y + s.z * s.z + s.w * s.w;
    #pragma unroll
    for (int off = 16; off > 0; off >>= 1)
        ss += __shfl_xor_sync(0xffffffff, ss, off);

    __shared__ float red[4];
    const int wd = tid >> 5, lane = tid & 31;
    if (lane == 0) red[wd] = ss;
    __syncthreads();
    const float tot = red[0] + red[1] + red[2] + red[3];
    const float scale = rsqrtf(tot * (1.0f / (float)DIM) + RMS_EPS);

    float4 vw = *(const float4*)(w + tid * 4);
    float4 o;
    o.x = s.x * scale * vw.x;
    o.y = s.y * scale * vw.y;
    o.z = s.z * scale * vw.z;
    o.w = s.w * scale * vw.w;
    if (out32) *(float4*)(out32 + base) = o;
    if (out16) {
        __half2* t = (__half2*)(out16 + base);
        t[0] = __floats2half2_rn(o.x, o.y);
        t[1] = __floats2half2_rn(o.z, o.w);
    }
}

// ---------------------------------------------------------------------------
extern "C" void kernel_launch(void* const* d_in, const int* in_sizes, int n_in,
                              void* d_out, int out_size)
{
    const float* x   = (const float*)d_in[0];
    const float* q   = (const float*)d_in[1];
    const float* k   = (const float*)d_in[2];
    const float* W1  = (const float*)d_in[3];
    const float* b1  = (const float*)d_in[4];
    const float* W2  = (const float*)d_in[5];
    const float* b2  = (const float*)d_in[6];
    const float* n1w = (const float*)d_in[7];
    const float* n2w = (const float*)d_in[8];
    float* out = (float*)d_out;

    __half *p16, *h16, *g16, *q16, *k16, *xT, *W1P, *W2T;
    cudaGetSymbolAddress((void**)&p16,    g_p16);
    cudaGetSymbolAddress((void**)&h16,    g_h16);
    cudaGetSymbolAddress((void**)&g16,    g_g16);
    cudaGetSymbolAddress((void**)&q16,    g_q16);
    cudaGetSymbolAddress((void**)&k16,    g_k16);
    cudaGetSymbolAddress((void**)&xT,     g_xT16);
    cudaGetSymbolAddress((void**)&W1P,    g_W1P);
    cudaGetSymbolAddress((void**)&W2T,    g_W2T);

    __half* attn16 = q16;   // q16 dead after GEMM1
    __half* ff16   = k16;   // k16 dead after GEMM1

    static int s_init = 0;
    static cudaStream_t s_side = nullptr;
    static cudaEvent_t s_fork, s_join;
    if (!s_init) {
        cudaFuncSetAttribute(gemm_f16mma<1>,
                             cudaFuncAttributeMaxDynamicSharedMemorySize, GEMM_SMEM);
        cudaFuncSetAttribute(gemm_f16mma<2>,
                             cudaFuncAttributeMaxDynamicSharedMemorySize, GEMM_SMEM);
        cudaFuncSetAttribute(gemm_f16mma<3>,
                             cudaFuncAttributeMaxDynamicSharedMemorySize, GEMM_SMEM);
        cudaFuncSetAttribute(gemm_f16mma<4>,
                             cudaFuncAttributeMaxDynamicSharedMemorySize, GEMM_SMEM_A);
        cudaStreamCreateWithFlags(&s_side, cudaStreamNonBlocking);
        cudaEventCreateWithFlags(&s_fork, cudaEventDisableTiming);
        cudaEventCreateWithFlags(&s_join, cudaEventDisableTiming);
        s_init = 1;
    }

    const float inv_sqrt_d = 0.044194173824159216f;  // 1/sqrt(512)

    // ---- fork: transposes (xT/W1P/W2T) run on side stream under GEMM1 ----
    cudaEventRecord(s_fork, 0);
    cudaStreamWaitEvent(s_side, s_fork, 0);
    {
        dim3 g(32, 64, 10);
        prep_transpose_kernel<<<g, 256, 0, s_side>>>(x, xT, W1, W1P, W2, W2T);
    }
    cudaEventRecord(s_join, s_side);

    // main stream: q,k convert then GEMM1 (needs only q16/k16)
    const int n4 = ROWS * DIM / 4;
    {
        dim3 g(n4 / 256, 2, 1);
        cvt2_f16_kernel<<<g, 256>>>((const float4*)q, (const float4*)k,
                                    (__half2*)q16, (__half2*)k16, n4);
    }

    // 1) p16 = exp(q @ k^T / sqrt(D))
    {
        dim3 grid(SEQ / BN, SEQ / BM, BATCH);
        gemm_f16mma<3><<<grid, 128, GEMM_SMEM>>>(
            q16, k16, nullptr, p16, SEQ, SEQ, DIM,
            (long long)SEQ * DIM, (long long)SEQ * DIM, (long long)SEQ * SEQ,
            inv_sqrt_d);
    }

    // ---- join: GEMM2 needs xT; later GEMMs need W1P/W2T ----
    cudaStreamWaitEvent(0, s_join, 0);

    // 2) attn16 = (p16 @ xT^T) / rowsum(p16)
    {
        dim3 grid(DIM / BN, SEQ / BM, BATCH);
        gemm_f16mma<4><<<grid, 128, GEMM_SMEM_A>>>(
            p16, xT, nullptr, attn16, SEQ, DIM, SEQ,
            (long long)SEQ * SEQ, (long long)SEQ * DIM, (long long)SEQ * DIM,
            1.0f);
    }

    // 3) h16 = rmsnorm(x + attn16, n1w)
    add_rmsnorm_kernel<0><<<ROWS, 128>>>(x, attn16, n1w, nullptr, h16);

    // 4+5) g16 = geglu(h16 @ W1P^T + b1)
    {
        dim3 grid((2 * DIM) / BN, ROWS / BM, 1);
        gemm_f16mma<2><<<grid, 128, GEMM_SMEM>>>(
            h16, W1P, b1, g16, ROWS, 2 * DIM, DIM, 0, 0, 0, 1.0f);
    }

    // 6) ff16 = g16 @ W2T^T + b2
    {
        dim3 grid(DIM / BN, ROWS / BM, 1);
        gemm_f16mma<1><<<grid, 128, GEMM_SMEM>>>(
            g16, W2T, b2, ff16, ROWS, DIM, DIM, 0, 0, 0, 1.0f);
    }

    // 7) out = rmsnorm(h16 + ff16, n2w) -> fp32 d_out
    add_rmsnorm_kernel<1><<<ROWS, 128>>>(h16, ff16, n2w, out, nullptr);
}

// round 17
// speedup vs baseline: 1.0572x; 1.0032x over previous
#include <cuda_runtime.h>
#include <cuda_fp16.h>
#include <math.h>
#include <stdint.h>

// ---------------------------------------------------------------------------
// XAIGuidedTransformerLayer on GB300 (sm_103a) — fp16 mma.sync GEMMs (fp32 acc).
// Round 17: R11 (best) + single merged prep launch that also emits fp16 x copy
// (rmsnorm1 reads fp16), no stream fork. GEMM core bit-identical to R11.
// B=8, S=2048, D=512.
// ---------------------------------------------------------------------------

#define BATCH 8
#define SEQ   2048
#define DIM   512
#define ROWS  (BATCH * SEQ)        // 16384
#define RMS_EPS 1.1920928955078125e-7f

// ---- scratch (device globals: allocation-free) ----
__device__ __half g_p16   [(size_t)BATCH * SEQ * SEQ];   // 67 MB fp16 exp(scores)
__device__ __half g_h16   [(size_t)ROWS * DIM];
__device__ __half g_g16   [(size_t)ROWS * DIM];
__device__ __half g_q16   [(size_t)ROWS * DIM];          // reused as attn16
__device__ __half g_k16   [(size_t)ROWS * DIM];          // reused as ff16
__device__ __half g_x16   [(size_t)ROWS * DIM];          // fp16 copy of x
__device__ __half g_xT16  [(size_t)ROWS * DIM];          // per-batch [D,S]
__device__ __half g_W1P   [(size_t)2 * DIM * DIM];       // [2D, D] col-interleaved
__device__ __half g_W2T   [(size_t)DIM * DIM];           // [D, D]

// ---------------------------------------------------------------------------
__device__ __forceinline__ uint32_t smem_u32(const void* p) {
    uint32_t a;
    asm("{ .reg .u64 t; cvta.to.shared.u64 t, %1; cvt.u32.u64 %0, t; }" : "=r"(a) : "l"(p));
    return a;
}

#define CP_ASYNC16(dst, src) \
    asm volatile("cp.async.cg.shared.global [%0], [%1], 16;" :: "r"(dst), "l"(src))
#define CP_COMMIT() asm volatile("cp.async.commit_group;")
#define CP_WAIT2()  asm volatile("cp.async.wait_group 2;")
#define CP_WAIT1()  asm volatile("cp.async.wait_group 1;")
#define CP_WAIT0()  asm volatile("cp.async.wait_group 0;")

#define LDSM4(r0, r1, r2, r3, addr) \
    asm volatile("ldmatrix.sync.aligned.m8n8.x4.shared.b16 {%0,%1,%2,%3}, [%4];" \
        : "=r"(r0), "=r"(r1), "=r"(r2), "=r"(r3) : "r"(addr))

#define MMA_F16(d, a0, a1, a2, a3, b0, b1) \
    asm volatile("mma.sync.aligned.m16n8k16.row.col.f32.f16.f16.f32 " \
        "{%0,%1,%2,%3}, {%4,%5,%6,%7}, {%8,%9}, {%0,%1,%2,%3};" \
        : "+f"((d)[0]), "+f"((d)[1]), "+f"((d)[2]), "+f"((d)[3]) \
        : "r"(a0), "r"(a1), "r"(a2), "r"(a3), "r"(b0), "r"(b1))

__device__ __forceinline__ float gelu_exact(float x) {
    return 0.5f * x * (1.0f + erff(x * 0.70710678118654752440f));
}

// ===========================================================================
// 128x128 tile GEMM (4 warps, warp tile 64x64), 4-stage single-barrier loop.
// MODE 1: fp16 out (alpha, optional fp32 bias).
// MODE 2: geglu out (W1 col-interleaved; output [M, N/2] fp16).
// MODE 3: fp16 out = exp(alpha * acc)    (attention scores -> e-values)
// MODE 4: rowsum(A) in mainloop; fp16 out = acc / rowsum   (attention PV)
// ===========================================================================
#define BM 128
#define BN 128
#define BKK 32
#define AST 40                     // padded row stride in halves (80 B)
#define TILE_B (BM * AST * 2)      // 10240 bytes per operand buffer
#define STAGES 4
#define BS_BASE (STAGES * TILE_B)
#define GEMM_SMEM   (2 * STAGES * TILE_B)        // 81920 bytes
#define GEMM_SMEM_A (GEMM_SMEM + 512)            // + rowsum[128] floats

template<int MODE>
__global__ void __launch_bounds__(128, 2)
gemm_f16mma(const __half* __restrict__ A, const __half* __restrict__ B,
            const float* __restrict__ bias, void* __restrict__ Cv,
            int M, int N, int K,
            long long sA, long long sB, long long sC, float alpha)
{
    extern __shared__ char smem[];
    const uint32_t sm = smem_u32(smem);
    float* rowsum_sm = (float*)(smem + GEMM_SMEM);   // MODE 4 only (128 floats)

    const int tid  = threadIdx.x;
    const int wid  = tid >> 5;
    const int lane = tid & 31;
    const int wm   = wid & 1;
    const int wn   = wid >> 1;

    A += (long long)blockIdx.z * sA;
    B += (long long)blockIdx.z * sB;
    const int row0 = blockIdx.y * BM;
    const int col0 = blockIdx.x * BN;

    const int c_r0 = (tid + 0)   >> 2, c_c0 = ((tid + 0)   & 3);
    const int c_r1 = (tid + 128) >> 2, c_c1 = ((tid + 128) & 3);
    const int c_r2 = (tid + 256) >> 2, c_c2 = ((tid + 256) & 3);
    const int c_r3 = (tid + 384) >> 2, c_c3 = ((tid + 384) & 3);

    const int q  = lane >> 3, r8 = lane & 7;
    const int arow = (q & 1) * 8 + r8;
    const int acol16 = (q >> 1);
    const int brow = (q >> 1) * 8 + r8;
    const int bcol16 = (q & 1);

    const uint32_t a_base = sm + (wm * 64 + arow) * (AST * 2) + acol16 * 16;
    const uint32_t b_base = sm + BS_BASE + (wn * 64 + brow) * (AST * 2) + bcol16 * 16;

    float acc[4][8][4];
    #pragma unroll
    for (int i = 0; i < 4; i++)
        #pragma unroll
        for (int j = 0; j < 8; j++)
            #pragma unroll
            for (int v = 0; v < 4; v++) acc[i][j][v] = 0.0f;

    float rsum[4][2];
    if (MODE == 4) {
        #pragma unroll
        for (int i = 0; i < 4; i++) { rsum[i][0] = 0.0f; rsum[i][1] = 0.0f; }
    }

    const int KT = K / BKK;

    auto load_tile = [&](int kt, int buf) {
        const long long k0 = (long long)kt * BKK;
        uint32_t da = sm + buf * TILE_B;
        uint32_t db = sm + BS_BASE + buf * TILE_B;
        CP_ASYNC16(da + c_r0 * 80 + c_c0 * 16, A + (long long)(row0 + c_r0) * K + k0 + c_c0 * 8);
        CP_ASYNC16(da + c_r1 * 80 + c_c1 * 16, A + (long long)(row0 + c_r1) * K + k0 + c_c1 * 8);
        CP_ASYNC16(da + c_r2 * 80 + c_c2 * 16, A + (long long)(row0 + c_r2) * K + k0 + c_c2 * 8);
        CP_ASYNC16(da + c_r3 * 80 + c_c3 * 16, A + (long long)(row0 + c_r3) * K + k0 + c_c3 * 8);
        CP_ASYNC16(db + c_r0 * 80 + c_c0 * 16, B + (long long)(col0 + c_r0) * K + k0 + c_c0 * 8);
        CP_ASYNC16(db + c_r1 * 80 + c_c1 * 16, B + (long long)(col0 + c_r1) * K + k0 + c_c1 * 8);
        CP_ASYNC16(db + c_r2 * 80 + c_c2 * 16, B + (long long)(col0 + c_r2) * K + k0 + c_c2 * 8);
        CP_ASYNC16(db + c_r3 * 80 + c_c3 * 16, B + (long long)(col0 + c_r3) * K + k0 + c_c3 * 8);
    };

    load_tile(0, 0); CP_COMMIT();
    load_tile(1, 1); CP_COMMIT();
    load_tile(2, 2); CP_COMMIT();

    for (int kt = 0; kt < KT; kt++) {
        const int rem = KT - 1 - kt;
        if (rem >= 2)      { CP_WAIT2(); }
        else if (rem == 1) { CP_WAIT1(); }
        else               { CP_WAIT0(); }
        __syncthreads();

        if (kt + 3 < KT) { load_tile(kt + 3, (kt + 3) & 3); CP_COMMIT(); }

        const uint32_t off = (kt & 3) * TILE_B;

        #pragma unroll
        for (int s = 0; s < 2; s++) {
            uint32_t af[4][4];
            #pragma unroll
            for (int i = 0; i < 4; i++)
                LDSM4(af[i][0], af[i][1], af[i][2], af[i][3],
                      a_base + off + i * (16 * AST * 2) + s * 32);

            if (MODE == 4) {
                if (wn == 0) {
                    #pragma unroll
                    for (int i = 0; i < 4; i++) {
                        __half2 s0 = __hadd2(*(const __half2*)&af[i][0],
                                             *(const __half2*)&af[i][2]);
                        __half2 s1 = __hadd2(*(const __half2*)&af[i][1],
                                             *(const __half2*)&af[i][3]);
                        float2 f0 = __half22float2(s0);
                        float2 f1 = __half22float2(s1);
                        rsum[i][0] += f0.x + f0.y;
                        rsum[i][1] += f1.x + f1.y;
                    }
                }
            }

            uint32_t bf[4][4];
            #pragma unroll
            for (int j = 0; j < 4; j++)
                LDSM4(bf[j][0], bf[j][1], bf[j][2], bf[j][3],
                      b_base + off + j * (16 * AST * 2) + s * 32);
            #pragma unroll
            for (int i = 0; i < 4; i++)
                #pragma unroll
                for (int jj = 0; jj < 8; jj++)
                    MMA_F16(acc[i][jj],
                            af[i][0], af[i][1], af[i][2], af[i][3],
                            bf[jj >> 1][(jj & 1) * 2], bf[jj >> 1][(jj & 1) * 2 + 1]);
        }
    }

    const int er = lane >> 2;
    const int ec = (lane & 3) * 2;

    if (MODE == 4) {
        if (wn == 0) {
            #pragma unroll
            for (int i = 0; i < 4; i++) {
                #pragma unroll
                for (int hh = 0; hh < 2; hh++) {
                    float v = rsum[i][hh];
                    v += __shfl_xor_sync(0xffffffff, v, 1);
                    v += __shfl_xor_sync(0xffffffff, v, 2);
                    if ((lane & 3) == 0)
                        rowsum_sm[wm * 64 + i * 16 + er + hh * 8] = v;
                }
            }
        }
        __syncthreads();
    }

    if (MODE == 1 || MODE == 3) {
        __half* C = (__half*)Cv + (long long)blockIdx.z * sC;
        #pragma unroll
        for (int i = 0; i < 4; i++) {
            const long long r0g = row0 + wm * 64 + i * 16 + er;
            #pragma unroll
            for (int jj = 0; jj < 8; jj++) {
                const int cg = col0 + wn * 64 + jj * 8 + ec;
                float v0, v1, v2, v3;
                if (MODE == 3) {
                    v0 = __expf(alpha * acc[i][jj][0]);
                    v1 = __expf(alpha * acc[i][jj][1]);
                    v2 = __expf(alpha * acc[i][jj][2]);
                    v3 = __expf(alpha * acc[i][jj][3]);
                } else {
                    float bx = 0.0f, by = 0.0f;
                    if (bias) { bx = bias[cg]; by = bias[cg + 1]; }
                    v0 = fmaf(alpha, acc[i][jj][0], bx);
                    v1 = fmaf(alpha, acc[i][jj][1], by);
                    v2 = fmaf(alpha, acc[i][jj][2], bx);
                    v3 = fmaf(alpha, acc[i][jj][3], by);
                }
                *(__half2*)(C + r0g * N + cg)       = __floats2half2_rn(v0, v1);
                *(__half2*)(C + (r0g + 8) * N + cg) = __floats2half2_rn(v2, v3);
            }
        }
    } else if (MODE == 4) {
        __half* C = (__half*)Cv + (long long)blockIdx.z * sC;
        #pragma unroll
        for (int i = 0; i < 4; i++) {
            const int rl = wm * 64 + i * 16 + er;
            const long long r0g = row0 + rl;
            const float inv0 = 1.0f / rowsum_sm[rl];
            const float inv1 = 1.0f / rowsum_sm[rl + 8];
            #pragma unroll
            for (int jj = 0; jj < 8; jj++) {
                const int cg = col0 + wn * 64 + jj * 8 + ec;
                *(__half2*)(C + r0g * N + cg) =
                    __floats2half2_rn(acc[i][jj][0] * inv0, acc[i][jj][1] * inv0);
                *(__half2*)(C + (r0g + 8) * N + cg) =
                    __floats2half2_rn(acc[i][jj][2] * inv1, acc[i][jj][3] * inv1);
            }
        }
    } else {                  // MODE 2: geglu epilogue
        __half* C = (__half*)Cv;    // [M, N/2]
        const int NO = N >> 1;
        #pragma unroll
        for (int i = 0; i < 4; i++) {
            const long long r0g = row0 + wm * 64 + i * 16 + er;
            #pragma unroll
            for (int jj = 0; jj < 8; jj += 2) {
                const int oc = ((col0 + wn * 64 + jj * 8) >> 1) + ec;
                const float b1x = bias[oc];
                const float b1y = bias[oc + 1];
                const float b2x = bias[512 + oc];
                const float b2y = bias[512 + oc + 1];
                float g0 = gelu_exact(acc[i][jj][0] + b1x) * (acc[i][jj + 1][0] + b2x);
                float g1 = gelu_exact(acc[i][jj][1] + b1y) * (acc[i][jj + 1][1] + b2y);
                float g2 = gelu_exact(acc[i][jj][2] + b1x) * (acc[i][jj + 1][2] + b2x);
                float g3 = gelu_exact(acc[i][jj][3] + b1y) * (acc[i][jj + 1][3] + b2y);
                *(__half2*)(C + r0g * NO + oc)       = __floats2half2_rn(g0, g1);
                *(__half2*)(C + (r0g + 8) * NO + oc) = __floats2half2_rn(g2, g3);
            }
        }
    }
}

// ---------------------------------------------------------------------------
// fp32 -> fp16 convert for q and k in one launch (grid.y selects tensor)
// ---------------------------------------------------------------------------
__global__ void __launch_bounds__(256)
cvt2_f16_kernel(const float4* __restrict__ q, const float4* __restrict__ k,
                __half2* __restrict__ q16, __half2* __restrict__ k16, int n4)
{
    int i = blockIdx.x * 256 + threadIdx.x;
    if (i >= n4) return;
    const float4* in = blockIdx.y ? k : q;
    __half2* out = blockIdx.y ? k16 : q16;
    float4 v = in[i];
    out[i * 2 + 0] = __floats2half2_rn(v.x, v.y);
    out[i * 2 + 1] = __floats2half2_rn(v.z, v.w);
}

// ---------------------------------------------------------------------------
// Merged prep (z selects tensor): z<8: x batch z -> xT AND contiguous x16;
// z=8: W1 (geglu interleave); z=9: W2.
// ---------------------------------------------------------------------------
__global__ void __launch_bounds__(256)
prep_transpose_kernel(const float* __restrict__ x,   __half* __restrict__ xT,
                      __half* __restrict__ x16,
                      const float* __restrict__ W1,  __half* __restrict__ W1P,
                      const float* __restrict__ W2,  __half* __restrict__ W2T)
{
    __shared__ float t[32][33];
    const float* in; __half* out;
    int R, C; long long zoff = 0; int perm = 0;
    const int z = blockIdx.z;
    const int bx = blockIdx.x, by = blockIdx.y;
    if (z < 8) {
        in = x; out = xT; R = SEQ; C = DIM; zoff = (long long)z * R * C; perm = 0;
        if (bx >= C / 32 || by >= R / 32) return;
    } else if (z == 8) {
        in = W1; out = W1P; R = DIM; C = 2 * DIM; zoff = 0; perm = 1;
        if (bx >= C / 32 || by >= R / 32) return;
    } else {
        in = W2; out = W2T; R = DIM; C = DIM; zoff = 0; perm = 0;
        if (bx >= C / 32 || by >= R / 32) return;
    }

    const int c0 = bx * 32, r0 = by * 32;
    const int tx = threadIdx.x & 31, ty = threadIdx.x >> 5;
    #pragma unroll
    for (int i = 0; i < 4; i++) {
        int rr = r0 + ty + i * 8;
        float v = in[zoff + (long long)rr * C + c0 + tx];
        t[ty + i * 8][tx] = v;
        if (z < 8)   // contiguous fp16 x copy (coalesced row-major write)
            x16[zoff + (long long)rr * C + c0 + tx] = __float2half_rn(v);
    }
    __syncthreads();
    #pragma unroll
    for (int i = 0; i < 4; i++) {
        int cc = c0 + ty + i * 8;
        int dr = cc;
        if (perm) {
            dr = (cc < 512) ? ((cc >> 3) << 4) + (cc & 7)
                            : (((cc - 512) >> 3) << 4) + 8 + ((cc - 512) & 7);
        }
        out[zoff + (long long)dr * R + r0 + tx] = __float2half_rn(t[tx][ty + i * 8]);
    }
}

// ---------------------------------------------------------------------------
// rmsnorm(a16 + b16) * w. Writes fp32 (out32) and/or fp16 (out16).
// ---------------------------------------------------------------------------
__global__ void __launch_bounds__(128)
add_rmsnorm16_kernel(const __half* __restrict__ a, const __half* __restrict__ b,
                     const float* __restrict__ w, float* __restrict__ out32,
                     __half* __restrict__ out16)
{
    const long long row = blockIdx.x;
    const int tid = threadIdx.x;
    const long long base = row * (long long)DIM + tid * 4;

    const __half2* ah = (const __half2*)(a + base);
    const __half2* bh = (const __half2*)(b + base);
    float2 a0 = __half22float2(ah[0]);
    float2 a1 = __half22float2(ah[1]);
    float2 b0 = __half22float2(bh[0]);
    float2 b1 = __half22float2(bh[1]);

    float4 s;
    s.x = a0.x + b0.x; s.y = a0.y + b0.y; s.z = a1.x + b1.x; s.w = a1.y + b1.y;

    float ss = s.x * s.x + s.y * s.y + s.z * s.z + s.w * s.w;
    #pragma unroll
    for (int off = 16; off > 0; off >>= 1)
        ss += __shfl_xor_sync(0xffffffff, ss, off);

    __shared__ float red[4];
    const int wd = tid >> 5, lane = tid & 31;
    if (lane == 0) red[wd] = ss;
    __syncthreads();
    const float tot = red[0] + red[1] + red[2] + red[3];
    const float scale = rsqrtf(tot * (1.0f / (float)DIM) + RMS_EPS);

    float4 vw = *(const float4*)(w + tid * 4);
    float4 o;
    o.x = s.x * scale * vw.x;
    o.y = s.y * scale * vw.y;
    o.z = s.z * scale * vw.z;
    o.w = s.w * scale * vw.w;
    if (out32) *(float4*)(out32 + base) = o;
    if (out16) {
        __half2* t = (__half2*)(out16 + base);
        t[0] = __floats2half2_rn(o.x, o.y);
        t[1] = __floats2half2_rn(o.z, o.w);
    }
}

// ---------------------------------------------------------------------------
extern "C" void kernel_launch(void* const* d_in, const int* in_sizes, int n_in,
                              void* d_out, int out_size)
{
    const float* x   = (const float*)d_in[0];
    const float* q   = (const float*)d_in[1];
    const float* k   = (const float*)d_in[2];
    const float* W1  = (const float*)d_in[3];
    const float* b1  = (const float*)d_in[4];
    const float* W2  = (const float*)d_in[5];
    const float* b2  = (const float*)d_in[6];
    const float* n1w = (const float*)d_in[7];
    const float* n2w = (const float*)d_in[8];
    float* out = (float*)d_out;

    __half *p16, *h16, *g16, *q16, *k16, *x16, *xT, *W1P, *W2T;
    cudaGetSymbolAddress((void**)&p16,    g_p16);
    cudaGetSymbolAddress((void**)&h16,    g_h16);
    cudaGetSymbolAddress((void**)&g16,    g_g16);
    cudaGetSymbolAddress((void**)&q16,    g_q16);
    cudaGetSymbolAddress((void**)&k16,    g_k16);
    cudaGetSymbolAddress((void**)&x16,    g_x16);
    cudaGetSymbolAddress((void**)&xT,     g_xT16);
    cudaGetSymbolAddress((void**)&W1P,    g_W1P);
    cudaGetSymbolAddress((void**)&W2T,    g_W2T);

    __half* attn16 = q16;   // q16 dead after GEMM1
    __half* ff16   = k16;   // k16 dead after GEMM1

    static int s_init = 0;
    if (!s_init) {
        cudaFuncSetAttribute(gemm_f16mma<1>,
                             cudaFuncAttributeMaxDynamicSharedMemorySize, GEMM_SMEM);
        cudaFuncSetAttribute(gemm_f16mma<2>,
                             cudaFuncAttributeMaxDynamicSharedMemorySize, GEMM_SMEM);
        cudaFuncSetAttribute(gemm_f16mma<3>,
                             cudaFuncAttributeMaxDynamicSharedMemorySize, GEMM_SMEM);
        cudaFuncSetAttribute(gemm_f16mma<4>,
                             cudaFuncAttributeMaxDynamicSharedMemorySize, GEMM_SMEM_A);
        s_init = 1;
    }

    const float inv_sqrt_d = 0.044194173824159216f;  // 1/sqrt(512)

    // prep: q,k -> fp16; merged x(->xT + x16)/W1/W2 transposes
    const int n4 = ROWS * DIM / 4;
    {
        dim3 g(n4 / 256, 2, 1);
        cvt2_f16_kernel<<<g, 256>>>((const float4*)q, (const float4*)k,
                                    (__half2*)q16, (__half2*)k16, n4);
    }
    {
        dim3 g(32, 64, 10);
        prep_transpose_kernel<<<g, 256>>>(x, xT, x16, W1, W1P, W2, W2T);
    }

    // 1) p16 = exp(q @ k^T / sqrt(D))
    {
        dim3 grid(SEQ / BN, SEQ / BM, BATCH);
        gemm_f16mma<3><<<grid, 128, GEMM_SMEM>>>(
            q16, k16, nullptr, p16, SEQ, SEQ, DIM,
            (long long)SEQ * DIM, (long long)SEQ * DIM, (long long)SEQ * SEQ,
            inv_sqrt_d);
    }

    // 2) attn16 = (p16 @ xT^T) / rowsum(p16)
    {
        dim3 grid(DIM / BN, SEQ / BM, BATCH);
        gemm_f16mma<4><<<grid, 128, GEMM_SMEM_A>>>(
            p16, xT, nullptr, attn16, SEQ, DIM, SEQ,
            (long long)SEQ * SEQ, (long long)SEQ * DIM, (long long)SEQ * DIM,
            1.0f);
    }

    // 3) h16 = rmsnorm(x16 + attn16, n1w)
    add_rmsnorm16_kernel<<<ROWS, 128>>>(x16, attn16, n1w, nullptr, h16);

    // 4+5) g16 = geglu(h16 @ W1P^T + b1)
    {
        dim3 grid((2 * DIM) / BN, ROWS / BM, 1);
        gemm_f16mma<2><<<grid, 128, GEMM_SMEM>>>(
            h16, W1P, b1, g16, ROWS, 2 * DIM, DIM, 0, 0, 0, 1.0f);
    }

    // 6) ff16 = g16 @ W2T^T + b2
    {
        dim3 grid(DIM / BN, ROWS / BM, 1);
        gemm_f16mma<1><<<grid, 128, GEMM_SMEM>>>(
            g16, W2T, b2, ff16, ROWS, DIM, DIM, 0, 0, 0, 1.0f);
    }

    // 7) out = rmsnorm(h16 + ff16, n2w) -> fp32 d_out
    add_rmsnorm16_kernel<<<ROWS, 128>>>(h16, ff16, n2w, out, nullptr);
}